// round 16
// baseline (speedup 1.0000x reference)
#include <cuda_runtime.h>
#include <cuda_fp16.h>
#include <cstdint>

#define M_DIM 8192
#define K_DIM 4096
#define N_DIM 11008
#define NG_DIM 32
#define KP_DIM 512
#define KSTR 4224                 /* K + 128 ext columns */
#define CH_K 64                   /* k-halves per chunk */
#define NCH  (KSTR / CH_K)        /* 66 = 3 * 22 */

#define TILE_M 128
#define TILE_N 128
#define NT (N_DIM / TILE_N) /* 86 */
#define MT (M_DIM / TILE_M) /* 64 */
#define NTHREADS 256

// ---------------- scratch (static device arrays: allocation-free) ----------------
__device__ __half g_A[(size_t)M_DIM * KSTR];    // fp16(x) + 128 ext cols (S hi,hi,lo,lo)
__device__ __half g_WT[(size_t)N_DIM * KSTR];   // fp16(nib*s) transposed [n][k] + ext rows

// ---------------- smem: 3 stages x (A 16KB + B 16KB), 128B rows, XOR swizzled ----------------
#define STAGE_A(s) ((uint32_t)(s) * 16384u)
#define STAGE_B(s) (49152u + (uint32_t)(s) * 16384u)
#define SMEM_BYTES 98304

// ---------------- helpers ----------------
__device__ __forceinline__ uint32_t smem_u32(const void* p) {
    uint32_t a;
    asm("{ .reg .u64 t; cvta.to.shared.u64 t, %1; cvt.u32.u64 %0, t; }" : "=r"(a) : "l"(p));
    return a;
}

#define CP_ASYNC16(dst, src) \
    asm volatile("cp.async.cg.shared.global [%0], [%1], 16;" :: "r"(dst), "l"(src))
#define CP_COMMIT()  asm volatile("cp.async.commit_group;" ::: "memory")
#define CP_WAIT1()   asm volatile("cp.async.wait_group 1;" ::: "memory")

#define LDSM_X4(r0, r1, r2, r3, addr) \
    asm volatile("ldmatrix.sync.aligned.m8n8.x4.shared.b16 {%0,%1,%2,%3}, [%4];" \
                 : "=r"(r0), "=r"(r1), "=r"(r2), "=r"(r3) : "r"(addr))

#define MMA16816(d, a, b0v, b1v) \
    asm volatile("mma.sync.aligned.m16n8k16.row.col.f32.f16.f16.f32 " \
                 "{%0,%1,%2,%3}, {%4,%5,%6,%7}, {%8,%9}, {%0,%1,%2,%3};" \
                 : "+f"((d)[0]), "+f"((d)[1]), "+f"((d)[2]), "+f"((d)[3]) \
                 : "r"((a)[0]), "r"((a)[1]), "r"((a)[2]), "r"((a)[3]), \
                   "r"(b0v), "r"(b1v))

// ---------------- prep 1: round x to fp16 into g_A + ext cols (fused) ----------------
__global__ void prep_kernel(const float* __restrict__ x) {
    int gwarp = (blockIdx.x * blockDim.x + threadIdx.x) >> 5;
    int lane  = threadIdx.x & 31;
    if (gwarp >= M_DIM * NG_DIM) return;
    int m = gwarp / NG_DIM;
    int g = gwarp % NG_DIM;
    const float* xr = x + (size_t)m * K_DIM + (size_t)g * 128;
    __half* ar = g_A + (size_t)m * KSTR + (size_t)g * 128;
    float sum = 0.f;
#pragma unroll
    for (int j = 0; j < 4; j++) {
        float v = xr[lane + 32 * j];
        __half hi = __float2half_rn(v);
        ar[lane + 32 * j] = hi;
        sum += __half2float(hi);
    }
#pragma unroll
    for (int o = 16; o > 0; o >>= 1) sum += __shfl_xor_sync(0xFFFFFFFFu, sum, o);
    if (lane == 0) {
        __half hi = __float2half_rn(sum);
        __half lo = __float2half_rn(sum - __half2float(hi));
        __half* er = g_A + (size_t)m * KSTR + 4096;
        er[g]      = hi;
        er[32 + g] = hi;
        er[64 + g] = lo;
        er[96 + g] = lo;
    }
}

// ---------------- prep 2: dequant W -> fp16(nib*s) [n][k] + zs ext rows (fused) ----------------
__global__ void prep_w_kernel(const int* __restrict__ Wq, const float* __restrict__ scales,
                              const float* __restrict__ zeros) {
    int idx = blockIdx.x * blockDim.x + threadIdx.x;
    if (idx >= N_DIM * KP_DIM) return;
    int n  = idx >> 9;            // / 512
    int kp = idx & 511;
    uint32_t w = (uint32_t)Wq[(size_t)kp * N_DIM + n];
    float s = scales[(size_t)(kp >> 4) * N_DIM + n];
    __half h[8];
#pragma unroll
    for (int j = 0; j < 8; j++) {
        float v = (float)((w >> (4 * j)) & 15u);
        h[j] = __float2half_rn(v * s);     // single rounding of exact product
    }
    *(uint4*)(g_WT + (size_t)n * KSTR + (size_t)kp * 8) = *(uint4*)h;

    if (kp < 32) {                 // zero-point ext rows, g = kp
        int g = kp;
        float sg = scales[(size_t)g * N_DIM + n];
        float zs = -zeros[(size_t)g * N_DIM + n] * sg;
        __half hi = __float2half_rn(zs);
        __half lo = __float2half_rn(zs - __half2float(hi));
        __half* r = g_WT + (size_t)n * KSTR + 4096;
        r[g]      = hi;   // pairs with A ext (S_hi)
        r[32 + g] = lo;   // pairs with S_hi
        r[64 + g] = hi;   // pairs with S_lo
        r[96 + g] = lo;   // => (S_hi+S_lo)*(zs_hi+zs_lo)
    }
}

// ---------------- cp.async one 128x64-half chunk (16KB), XOR-swizzled ----------------
__device__ __forceinline__ void cp_chunk(uint32_t dbuf, const __half* __restrict__ gsrc,
                                         int row0, int ch, int tid) {
#pragma unroll
    for (int i = 0; i < 4; i++) {
        int idx = tid + i * NTHREADS;     // 0..1023 16B pieces
        int row = idx >> 3;
        int c   = idx & 7;
        const char* src = (const char*)(gsrc + (size_t)(row0 + row) * KSTR
                                        + (size_t)ch * CH_K + (size_t)c * 8);
        CP_ASYNC16(dbuf + (uint32_t)row * 128u + (uint32_t)((c ^ (row & 7)) << 4), src);
    }
}

// ---------------- main GEMM: fp16 GEMM over K=4224, 3-stage, B-frag double-buffer ----------------
__global__ void __launch_bounds__(NTHREADS, 2)
gemm_kernel(float* __restrict__ out) {
    extern __shared__ char smem[];
    uint32_t sb = smem_u32(smem);
    int tid  = threadIdx.x;
    int wid  = tid >> 5;          // 0..7
    int lane = tid & 31;
    int wm   = wid >> 2;          // 0..1 -> 64 m-rows
    int wn   = wid & 3;           // 0..3 -> 32 n-cols

    int n0 = blockIdx.x * TILE_N;
    int m0 = blockIdx.y * TILE_M;

    float acc[4][4][4];
#pragma unroll
    for (int tm = 0; tm < 4; tm++)
#pragma unroll
        for (int tn = 0; tn < 4; tn++)
#pragma unroll
            for (int c = 0; c < 4; c++) acc[tm][tn][c] = 0.f;

    // ldmatrix lane addressing (swizzled 128B rows)
    int s7 = lane & 7;
    int hA = lane >> 4;
    int hB = (lane >> 3) & 1;
    uint32_t offA[4];
#pragma unroll
    for (int tm = 0; tm < 4; tm++) {
        int rowA = wm * 64 + tm * 16 + (lane & 15);
        offA[tm] = (uint32_t)rowA * 128u;
    }
    uint32_t offB[2];
#pragma unroll
    for (int j = 0; j < 2; j++) {
        int rowB = wn * 32 + j * 16 + ((lane >> 4) << 3) + (lane & 7);
        offB[j] = (uint32_t)rowB * 128u;
    }

    // ---------------- prologue: stage chunks 0 and 1 ----------------
    cp_chunk(sb + STAGE_A(0), g_A, m0, 0, tid);
    cp_chunk(sb + STAGE_B(0), g_WT, n0, 0, tid);
    CP_COMMIT();
    cp_chunk(sb + STAGE_A(1), g_A, m0, 1, tid);
    cp_chunk(sb + STAGE_B(1), g_WT, n0, 1, tid);
    CP_COMMIT();

    // One iteration: compute chunk CH from stage SCUR; prefetch CH+2 into SNXT2.
    // B fragments double-buffered across k16 steps; first B LDSM issues BEFORE the
    // cp.async burst so compute gets the crossbar first.
#define ITER(CH, SCUR, SNXT2)                                                      \
    do {                                                                           \
        CP_WAIT1();                                                                \
        __syncthreads();                                                           \
        uint32_t aB = sb + STAGE_A(SCUR);                                          \
        uint32_t bB = sb + STAGE_B(SCUR);                                          \
        uint32_t bb[2][8];                                                         \
        {                                                                          \
            uint32_t cB0 = (uint32_t)((hB ^ s7) << 4);                             \
            LDSM_X4(bb[0][0], bb[0][1], bb[0][2], bb[0][3], bB + offB[0] + cB0);   \
            LDSM_X4(bb[0][4], bb[0][5], bb[0][6], bb[0][7], bB + offB[1] + cB0);   \
        }                                                                          \
        if ((CH) + 2 < NCH) {                                                      \
            cp_chunk(sb + STAGE_A(SNXT2), g_A, m0, (CH) + 2, tid);                 \
            cp_chunk(sb + STAGE_B(SNXT2), g_WT, n0, (CH) + 2, tid);                \
        }                                                                          \
        CP_COMMIT();                                                               \
        _Pragma("unroll")                                                          \
        for (int k16 = 0; k16 < 4; k16++) {                                        \
            int cur = k16 & 1;                                                     \
            if (k16 < 3) {                                                         \
                uint32_t cBn = (uint32_t)(((2 * (k16 + 1) + hB) ^ s7) << 4);       \
                LDSM_X4(bb[cur ^ 1][0], bb[cur ^ 1][1], bb[cur ^ 1][2],            \
                        bb[cur ^ 1][3], bB + offB[0] + cBn);                       \
                LDSM_X4(bb[cur ^ 1][4], bb[cur ^ 1][5], bb[cur ^ 1][6],            \
                        bb[cur ^ 1][7], bB + offB[1] + cBn);                       \
            }                                                                      \
            uint32_t cA = (uint32_t)(((2 * k16 + hA) ^ s7) << 4);                  \
            _Pragma("unroll")                                                      \
            for (int tm = 0; tm < 4; tm++) {                                       \
                uint32_t a[4];                                                     \
                LDSM_X4(a[0], a[1], a[2], a[3], aB + offA[tm] + cA);               \
                MMA16816(acc[tm][0], a, bb[cur][0], bb[cur][1]);                   \
                MMA16816(acc[tm][1], a, bb[cur][2], bb[cur][3]);                   \
                MMA16816(acc[tm][2], a, bb[cur][4], bb[cur][5]);                   \
                MMA16816(acc[tm][3], a, bb[cur][6], bb[cur][7]);                   \
            }                                                                      \
        }                                                                          \
    } while (0)

    for (int ch = 0; ch < NCH; ch += 3) {
        ITER(ch,     0, 2);
        ITER(ch + 1, 1, 0);
        ITER(ch + 2, 2, 1);
    }
#undef ITER

    // ---- store output ----
#pragma unroll
    for (int tm = 0; tm < 4; tm++) {
        int r1 = m0 + wm * 64 + tm * 16 + (lane >> 2);
#pragma unroll
        for (int tn = 0; tn < 4; tn++) {
            int nc = n0 + wn * 32 + tn * 8 + (lane & 3) * 2;
            *(float2*)(out + (size_t)r1 * N_DIM + nc)       = make_float2(acc[tm][tn][0], acc[tm][tn][1]);
            *(float2*)(out + (size_t)(r1 + 8) * N_DIM + nc) = make_float2(acc[tm][tn][2], acc[tm][tn][3]);
        }
    }
}

// ---------------- launch ----------------
extern "C" void kernel_launch(void* const* d_in, const int* in_sizes, int n_in,
                              void* d_out, int out_size) {
    const float* x      = (const float*)d_in[0];
    const int*   Wq     = (const int*)d_in[1];
    const float* scales = (const float*)d_in[2];
    const float* zeros  = (const float*)d_in[3];
    float* out = (float*)d_out;

    cudaFuncSetAttribute(gemm_kernel, cudaFuncAttributeMaxDynamicSharedMemorySize, SMEM_BYTES);

    prep_kernel<<<(M_DIM * NG_DIM * 32) / 256, 256>>>(x);
    prep_w_kernel<<<(N_DIM * KP_DIM) / 256, 256>>>(Wq, scales, zeros);

    dim3 grid(NT, MT);
    gemm_kernel<<<grid, NTHREADS, SMEM_BYTES>>>(out);
}

// round 17
// speedup vs baseline: 1.0022x; 1.0022x over previous
#include <cuda_runtime.h>
#include <cuda_fp16.h>
#include <cstdint>

#define M_DIM 8192
#define K_DIM 4096
#define N_DIM 11008
#define NG_DIM 32
#define KP_DIM 512
#define KSTR 4224                 /* K + 128 ext columns */
#define CH_K 64                   /* k-halves per chunk */
#define NCH  (KSTR / CH_K)        /* 66 chunks = 33 pairs */

#define TILE_M 128
#define TILE_N 256
#define NT (N_DIM / TILE_N) /* 43 */
#define MT (M_DIM / TILE_M) /* 64 */
#define NTHREADS 512

// ---------------- scratch (static device arrays: allocation-free) ----------------
__device__ __half g_A[(size_t)M_DIM * KSTR];    // fp16(x) + 128 ext cols (S hi,hi,lo,lo)
__device__ __half g_WT[(size_t)N_DIM * KSTR];   // fp16(nib*s) transposed [n][k] + ext rows

// ---------------- smem: 4 stages x (A 16KB + B 32KB), 128B rows, XOR swizzled ----------------
#define STG_SZ 49152u
#define SMEM_BYTES 196608

// ---------------- helpers ----------------
__device__ __forceinline__ uint32_t smem_u32(const void* p) {
    uint32_t a;
    asm("{ .reg .u64 t; cvta.to.shared.u64 t, %1; cvt.u32.u64 %0, t; }" : "=r"(a) : "l"(p));
    return a;
}

#define CP_ASYNC16(dst, src) \
    asm volatile("cp.async.cg.shared.global [%0], [%1], 16;" :: "r"(dst), "l"(src))
#define CP_COMMIT()  asm volatile("cp.async.commit_group;" ::: "memory")
#define CP_WAIT0()   asm volatile("cp.async.wait_group 0;" ::: "memory")

#define LDSM_X4(r0, r1, r2, r3, addr) \
    asm volatile("ldmatrix.sync.aligned.m8n8.x4.shared.b16 {%0,%1,%2,%3}, [%4];" \
                 : "=r"(r0), "=r"(r1), "=r"(r2), "=r"(r3) : "r"(addr))

#define MMA16816(d, a, b0v, b1v) \
    asm volatile("mma.sync.aligned.m16n8k16.row.col.f32.f16.f16.f32 " \
                 "{%0,%1,%2,%3}, {%4,%5,%6,%7}, {%8,%9}, {%0,%1,%2,%3};" \
                 : "+f"((d)[0]), "+f"((d)[1]), "+f"((d)[2]), "+f"((d)[3]) \
                 : "r"((a)[0]), "r"((a)[1]), "r"((a)[2]), "r"((a)[3]), \
                   "r"(b0v), "r"(b1v))

// ---------------- prep 1: round x to fp16 into g_A + ext cols (fused) ----------------
__global__ void prep_kernel(const float* __restrict__ x) {
    int gwarp = (blockIdx.x * blockDim.x + threadIdx.x) >> 5;
    int lane  = threadIdx.x & 31;
    if (gwarp >= M_DIM * NG_DIM) return;
    int m = gwarp / NG_DIM;
    int g = gwarp % NG_DIM;
    const float* xr = x + (size_t)m * K_DIM + (size_t)g * 128;
    __half* ar = g_A + (size_t)m * KSTR + (size_t)g * 128;
    float sum = 0.f;
#pragma unroll
    for (int j = 0; j < 4; j++) {
        float v = xr[lane + 32 * j];
        __half hi = __float2half_rn(v);
        ar[lane + 32 * j] = hi;
        sum += __half2float(hi);
    }
#pragma unroll
    for (int o = 16; o > 0; o >>= 1) sum += __shfl_xor_sync(0xFFFFFFFFu, sum, o);
    if (lane == 0) {
        __half hi = __float2half_rn(sum);
        __half lo = __float2half_rn(sum - __half2float(hi));
        __half* er = g_A + (size_t)m * KSTR + 4096;
        er[g]      = hi;
        er[32 + g] = hi;
        er[64 + g] = lo;
        er[96 + g] = lo;
    }
}

// ---------------- prep 2: dequant W -> fp16(nib*s) [n][k] + zs ext rows (fused) ----------------
__global__ void prep_w_kernel(const int* __restrict__ Wq, const float* __restrict__ scales,
                              const float* __restrict__ zeros) {
    int idx = blockIdx.x * blockDim.x + threadIdx.x;
    if (idx >= N_DIM * KP_DIM) return;
    int n  = idx >> 9;            // / 512
    int kp = idx & 511;
    uint32_t w = (uint32_t)Wq[(size_t)kp * N_DIM + n];
    float s = scales[(size_t)(kp >> 4) * N_DIM + n];
    __half h[8];
#pragma unroll
    for (int j = 0; j < 8; j++) {
        float v = (float)((w >> (4 * j)) & 15u);
        h[j] = __float2half_rn(v * s);     // single rounding of exact product
    }
    *(uint4*)(g_WT + (size_t)n * KSTR + (size_t)kp * 8) = *(uint4*)h;

    if (kp < 32) {                 // zero-point ext rows, g = kp
        int g = kp;
        float sg = scales[(size_t)g * N_DIM + n];
        float zs = -zeros[(size_t)g * N_DIM + n] * sg;
        __half hi = __float2half_rn(zs);
        __half lo = __float2half_rn(zs - __half2float(hi));
        __half* r = g_WT + (size_t)n * KSTR + 4096;
        r[g]      = hi;   // pairs with A ext (S_hi)
        r[32 + g] = lo;   // pairs with S_hi
        r[64 + g] = hi;   // pairs with S_lo
        r[96 + g] = lo;   // => (S_hi+S_lo)*(zs_hi+zs_lo)
    }
}

// ---------------- cp.async A chunk (128 rows x 64 halves, 16KB) ----------------
__device__ __forceinline__ void cp_a(uint32_t dbuf, int m0, int ch, int tid) {
#pragma unroll
    for (int i = 0; i < 2; i++) {
        int idx = tid + i * NTHREADS;     // 0..1023 16B pieces
        int row = idx >> 3;
        int c   = idx & 7;
        const char* src = (const char*)(g_A + (size_t)(m0 + row) * KSTR
                                        + (size_t)ch * CH_K + (size_t)c * 8);
        CP_ASYNC16(dbuf + (uint32_t)row * 128u + (uint32_t)((c ^ (row & 7)) << 4), src);
    }
}

// ---------------- cp.async B chunk (256 rows x 64 halves, 32KB) ----------------
__device__ __forceinline__ void cp_b(uint32_t dbuf, int n0, int ch, int tid) {
#pragma unroll
    for (int i = 0; i < 4; i++) {
        int idx = tid + i * NTHREADS;     // 0..2047 16B pieces
        int row = idx >> 3;
        int c   = idx & 7;
        const char* src = (const char*)(g_WT + (size_t)(n0 + row) * KSTR
                                        + (size_t)ch * CH_K + (size_t)c * 8);
        CP_ASYNC16(dbuf + (uint32_t)row * 128u + (uint32_t)((c ^ (row & 7)) << 4), src);
    }
}

// ---------------- main GEMM: 128x256 CTA, 16 warps (4m x 4n), warp 32m x 64n ----------------
__global__ void __launch_bounds__(NTHREADS, 1)
gemm_kernel(float* __restrict__ out) {
    extern __shared__ char smem[];
    uint32_t sb = smem_u32(smem);
    int tid  = threadIdx.x;
    int wid  = tid >> 5;          // 0..15
    int lane = tid & 31;
    int wm   = wid >> 2;          // 0..3 -> 32 m-rows
    int wn   = wid & 3;           // 0..3 -> 64 n-cols

    int n0 = blockIdx.x * TILE_N;
    int m0 = blockIdx.y * TILE_M;

    float acc[2][8][4];
#pragma unroll
    for (int tm = 0; tm < 2; tm++)
#pragma unroll
        for (int tn = 0; tn < 8; tn++)
#pragma unroll
            for (int c = 0; c < 4; c++) acc[tm][tn][c] = 0.f;

    // ldmatrix lane addressing (swizzled 128B rows)
    int s7 = lane & 7;
    int hA = lane >> 4;
    int hB = (lane >> 3) & 1;
    uint32_t offA[2];
#pragma unroll
    for (int tm = 0; tm < 2; tm++) {
        int rowA = wm * 32 + tm * 16 + (lane & 15);
        offA[tm] = (uint32_t)rowA * 128u;
    }
    uint32_t offB[4];
#pragma unroll
    for (int j = 0; j < 4; j++) {
        int rowB = wn * 64 + j * 16 + ((lane >> 4) << 3) + (lane & 7);
        offB[j] = (uint32_t)rowB * 128u;
    }

    // ---------------- prologue: stage chunks 0 and 1 ----------------
    cp_a(sb + 0 * STG_SZ, m0, 0, tid);
    cp_b(sb + 0 * STG_SZ + 16384u, n0, 0, tid);
    CP_COMMIT();
    cp_a(sb + 1 * STG_SZ, m0, 1, tid);
    cp_b(sb + 1 * STG_SZ + 16384u, n0, 1, tid);
    CP_COMMIT();

    // compute one chunk from stage (runtime) sOff; caller handles prefetch/commit
#define COMPUTE_CHUNK(sOff)                                                        \
    do {                                                                           \
        uint32_t aB = sb + (sOff);                                                 \
        uint32_t bB = aB + 16384u;                                                 \
        _Pragma("unroll")                                                          \
        for (int k16 = 0; k16 < 4; k16++) {                                        \
            uint32_t b[16];                                                        \
            uint32_t cB = (uint32_t)(((2 * k16 + hB) ^ s7) << 4);                  \
            _Pragma("unroll")                                                      \
            for (int j = 0; j < 4; j++)                                            \
                LDSM_X4(b[4 * j], b[4 * j + 1], b[4 * j + 2], b[4 * j + 3],        \
                        bB + offB[j] + cB);                                        \
            uint32_t cA = (uint32_t)(((2 * k16 + hA) ^ s7) << 4);                  \
            _Pragma("unroll")                                                      \
            for (int tm = 0; tm < 2; tm++) {                                       \
                uint32_t a[4];                                                     \
                LDSM_X4(a[0], a[1], a[2], a[3], aB + offA[tm] + cA);               \
                _Pragma("unroll")                                                  \
                for (int tn = 0; tn < 8; tn++)                                     \
                    MMA16816(acc[tm][tn], a, b[2 * tn], b[2 * tn + 1]);            \
            }                                                                      \
        }                                                                          \
    } while (0)

    // 33 pairs; one barrier per pair; prefetch distance 2 over 4 stages
    for (int chp = 0; chp < NCH / 2; chp++) {
        int c0 = 2 * chp;
        uint32_t so = (uint32_t)(chp & 1) * (2u * STG_SZ);   // stage of c0: 0 or 2

        CP_WAIT0();
        __syncthreads();

        // chunk c0: prefetch c0+2 into stage (c0+2)%4
        if (c0 + 2 < NCH) {
            uint32_t pd = sb + (so ^ (2u * STG_SZ));
            cp_a(pd, m0, c0 + 2, tid);
            cp_b(pd + 16384u, n0, c0 + 2, tid);
        }
        CP_COMMIT();
        COMPUTE_CHUNK(so);

        // chunk c0+1: prefetch c0+3 into stage (c0+3)%4
        if (c0 + 3 < NCH) {
            uint32_t pd = sb + (so ^ (2u * STG_SZ)) + STG_SZ;
            cp_a(pd, m0, c0 + 3, tid);
            cp_b(pd + 16384u, n0, c0 + 3, tid);
        }
        CP_COMMIT();
        COMPUTE_CHUNK(so + STG_SZ);
    }
#undef COMPUTE_CHUNK

    // ---- store output ----
#pragma unroll
    for (int tm = 0; tm < 2; tm++) {
        int r1 = m0 + wm * 32 + tm * 16 + (lane >> 2);
#pragma unroll
        for (int tn = 0; tn < 8; tn++) {
            int nc = n0 + wn * 64 + tn * 8 + (lane & 3) * 2;
            *(float2*)(out + (size_t)r1 * N_DIM + nc)       = make_float2(acc[tm][tn][0], acc[tm][tn][1]);
            *(float2*)(out + (size_t)(r1 + 8) * N_DIM + nc) = make_float2(acc[tm][tn][2], acc[tm][tn][3]);
        }
    }
}

// ---------------- launch ----------------
extern "C" void kernel_launch(void* const* d_in, const int* in_sizes, int n_in,
                              void* d_out, int out_size) {
    const float* x      = (const float*)d_in[0];
    const int*   Wq     = (const int*)d_in[1];
    const float* scales = (const float*)d_in[2];
    const float* zeros  = (const float*)d_in[3];
    float* out = (float*)d_out;

    cudaFuncSetAttribute(gemm_kernel, cudaFuncAttributeMaxDynamicSharedMemorySize, SMEM_BYTES);

    prep_kernel<<<(M_DIM * NG_DIM * 32) / 256, 256>>>(x);
    prep_w_kernel<<<(N_DIM * KP_DIM) / 256, 256>>>(Wq, scales, zeros);

    dim3 grid(NT, MT);
    gemm_kernel<<<grid, NTHREADS, SMEM_BYTES>>>(out);
}